// round 2
// baseline (speedup 1.0000x reference)
#include <cuda_runtime.h>
#include <math.h>

#define LQ    512
#define KNN   64
#define DM    256
#define DP    128
#define DS    32
#define NL0   32
#define NRBF  36
#define MH    64
#define MOUT  38

// ---------------- scratch (static device arrays; no allocation) ----------------
__device__ float g_node_feat[LQ * NL0];
__device__ int   g_nbr[LQ * KNN];

__device__ __forceinline__ float wsum(float v) {
#pragma unroll
    for (int o = 16; o; o >>= 1) v += __shfl_xor_sync(0xffffffffu, v, o);
    return v;
}

// ---------------- Kernel A: per-residue node features ----------------
// node = LN(concat(LN(msa), seq1hot, LN(state)) @ W_x + b_x)
__global__ void __launch_bounds__(32) node_kernel(
    const float* __restrict__ msa, const float* __restrict__ seq1hot,
    const float* __restrict__ state,
    const float* __restrict__ g_msa, const float* __restrict__ b_msa,
    const float* __restrict__ g_state, const float* __restrict__ b_state,
    const float* __restrict__ W_x, const float* __restrict__ b_x,
    const float* __restrict__ g_node, const float* __restrict__ b_node)
{
    int l = blockIdx.x;
    int lane = threadIdx.x;
    __shared__ float sx[DM + 21 + DS];   // 309

    // LN over msa (256)
    float m[8]; float s0 = 0.f;
#pragma unroll
    for (int q = 0; q < 8; q++) { m[q] = msa[l * DM + lane + 32 * q]; s0 += m[q]; }
    float mu = wsum(s0) * (1.f / DM);
    float v0 = 0.f;
#pragma unroll
    for (int q = 0; q < 8; q++) { float d = m[q] - mu; v0 += d * d; }
    float rs = rsqrtf(wsum(v0) * (1.f / DM) + 1e-5f);
#pragma unroll
    for (int q = 0; q < 8; q++) {
        int c = lane + 32 * q;
        sx[c] = (m[q] - mu) * rs * g_msa[c] + b_msa[c];
    }
    if (lane < 21) sx[DM + lane] = seq1hot[l * 21 + lane];
    {
        float st = state[l * DS + lane];
        float mu2 = wsum(st) * (1.f / DS);
        float d = st - mu2;
        float rs2 = rsqrtf(wsum(d * d) * (1.f / DS) + 1e-5f);
        sx[DM + 21 + lane] = d * rs2 * g_state[lane] + b_state[lane];
    }
    __syncwarp();

    // 309 x 32 matvec
    float acc = b_x[lane];
    for (int c = 0; c < DM + 21 + DS; c++)
        acc = fmaf(sx[c], W_x[c * NL0 + lane], acc);

    // LN32
    float mu3 = wsum(acc) * (1.f / NL0);
    float d3 = acc - mu3;
    float rs3 = rsqrtf(wsum(d3 * d3) * (1.f / NL0) + 1e-5f);
    g_node_feat[l * NL0 + lane] = d3 * rs3 * g_node[lane] + b_node[lane];
}

// ---------------- Kernel B: kNN via full bitonic sort per residue ----------------
__global__ void __launch_bounds__(256) topk_kernel(const float* __restrict__ xyz)
{
    int i = blockIdx.x;
    int tid = threadIdx.x;
    __shared__ float sca[LQ * 3];
    __shared__ unsigned long long keys[LQ];

    for (int j = tid; j < LQ; j += 256) {
        sca[j * 3 + 0] = xyz[j * 9 + 3];
        sca[j * 3 + 1] = xyz[j * 9 + 4];
        sca[j * 3 + 2] = xyz[j * 9 + 5];
    }
    __syncthreads();
    float cx = sca[i * 3 + 0], cy = sca[i * 3 + 1], cz = sca[i * 3 + 2];
    for (int j = tid; j < LQ; j += 256) {
        float dx = sca[j * 3 + 0] - cx, dy = sca[j * 3 + 1] - cy, dz = sca[j * 3 + 2] - cz;
        float d2 = dx * dx + dy * dy + dz * dz;
        if (j == i) d2 += 1e9f;
        keys[j] = (((unsigned long long)__float_as_uint(d2)) << 32) | (unsigned)j;
    }
    // bitonic sort ascending (512 keys, 256 threads)
    for (int k = 2; k <= LQ; k <<= 1) {
        for (int j = k >> 1; j > 0; j >>= 1) {
            __syncthreads();
            for (int t = tid; t < LQ; t += 256) {
                int ixj = t ^ j;
                if (ixj > t) {
                    unsigned long long a = keys[t], b = keys[ixj];
                    bool up = ((t & k) == 0);
                    bool sw = up ? (a > b) : (a < b);
                    if (sw) { keys[t] = b; keys[ixj] = a; }
                }
            }
        }
    }
    __syncthreads();
    if (tid < KNN) g_nbr[i * KNN + tid] = (int)(keys[tid] & 0xffffffffull);
}

// ---------------- Kernel C: per-residue edge MLP + epilogue ----------------
// smem layout (floats)
#define OFF_WE1    0        // 128*32
#define OFF_W1     4096     // 135*64
#define OFF_W2P    12736    // 64*48 (W2 padded to 48 cols)
#define OFF_INVT   15808    // 103*65 invT2[cc][pair], cc = feature-32
#define OFF_BUF    22504    // max(pnT 128*65, hT 64*65) = 8320
#define OFF_HBASE  30824    // 64
#define OFF_BE1    30888    // 32
#define OFF_GNE1   30920    // 32
#define OFF_BNE1   30952    // 32
#define OFF_GP     30984    // 128
#define OFF_BP     31112    // 128
#define OFF_B2P    31240    // 48
#define OFF_NODEI  31288    // 32
#define OFF_CA     31320    // 4
#define OFF_WV     31324    // 12
#define OFF_NBR    31336    // 64 (ints)
#define OFF_RELHAT 31400    // 64*3
#define OFF_GVGD   31592    // 64*6
#define OFF_M0S    31976    // 32
#define OFF_O1S    32008    // 12
#define SMEMF      32020

__global__ void __launch_bounds__(256) pair_kernel(
    const float* __restrict__ xyz, const float* __restrict__ pair,
    const float* __restrict__ g_pair, const float* __restrict__ b_pair,
    const float* __restrict__ W_e1, const float* __restrict__ b_e1,
    const float* __restrict__ g_ne1, const float* __restrict__ b_ne1,
    const float* __restrict__ W1, const float* __restrict__ b1,
    const float* __restrict__ W2, const float* __restrict__ b2,
    const float* __restrict__ Wv, const float* __restrict__ Wself,
    const float* __restrict__ W_lddt, const float* __restrict__ b_lddt,
    const float* __restrict__ g_state, const float* __restrict__ b_state,
    float* __restrict__ out)
{
    extern __shared__ float s[];
    int l = blockIdx.x;
    int tid = threadIdx.x;
    int w = tid >> 5, lane = tid & 31;

    // ---- stage weights & vectors ----
    for (int i = tid; i < 4096; i += 256) s[OFF_WE1 + i] = W_e1[i];
    for (int i = tid; i < 8640; i += 256) s[OFF_W1 + i] = W1[i];
    for (int i = tid; i < 3072; i += 256) {
        int h = i / 48, c = i - h * 48;
        s[OFF_W2P + i] = (c < MOUT) ? W2[h * MOUT + c] : 0.f;
    }
    if (tid < 32) {
        s[OFF_BE1 + tid] = b_e1[tid];
        s[OFF_GNE1 + tid] = g_ne1[tid];
        s[OFF_BNE1 + tid] = b_ne1[tid];
        s[OFF_NODEI + tid] = g_node_feat[l * NL0 + tid];
        s[OFF_M0S + tid] = 0.f;
    }
    if (tid < 12) s[OFF_O1S + tid] = 0.f;
    if (tid < 128) { s[OFF_GP + tid] = g_pair[tid]; s[OFF_BP + tid] = b_pair[tid]; }
    if (tid < 48) s[OFF_B2P + tid] = (tid < MOUT) ? b2[tid] : 0.f;
    if (tid < 64) ((int*)(s + OFF_NBR))[tid] = g_nbr[l * KNN + tid];
    if (tid < 3) s[OFF_CA + tid] = xyz[l * 9 + 3 + tid];
    if (tid < 9) s[OFF_WV + tid] = Wv[tid];
    __syncthreads();

    // ---- hbase: node_i part of MLP1 (same for all pairs) ----
    if (tid < 64) {
        float a = b1[tid];
#pragma unroll
        for (int c = 0; c < 32; c++)
            a = fmaf(s[OFF_NODEI + c], s[OFF_W1 + c * 64 + tid], a);
        s[OFF_HBASE + tid] = a;
    }

    // ---- per-pair prep: pair-row LN -> pnT, node_j, rbf, vnorm, relhat ----
    float ca0 = s[OFF_CA + 0], ca1 = s[OFF_CA + 1], ca2 = s[OFF_CA + 2];
    for (int t = 0; t < 8; t++) {
        int p = t * 8 + w;
        int j = ((const int*)(s + OFF_NBR))[p];
        const float* prow = pair + ((size_t)l * LQ + j) * DP;
        float pv[4]; float sm = 0.f;
#pragma unroll
        for (int q = 0; q < 4; q++) { pv[q] = prow[lane + 32 * q]; sm += pv[q]; }
        float mu = wsum(sm) * (1.f / DP);
        float vv = 0.f;
#pragma unroll
        for (int q = 0; q < 4; q++) { float d = pv[q] - mu; vv += d * d; }
        float rs = rsqrtf(wsum(vv) * (1.f / DP) + 1e-5f);
#pragma unroll
        for (int q = 0; q < 4; q++) {
            int c = lane + 32 * q;
            s[OFF_BUF + c * 65 + p] = (pv[q] - mu) * rs * s[OFF_GP + c] + s[OFF_BP + c];
        }
        // node_j -> invT2 rows 0..31
        s[OFF_INVT + lane * 65 + p] = g_node_feat[j * NL0 + lane];
        // geometry
        float cj0 = xyz[j * 9 + 3], cj1 = xyz[j * 9 + 4], cj2 = xyz[j * 9 + 5];
        float r0 = cj0 - ca0, r1 = cj1 - ca1, r2 = cj2 - ca2;
        float r = sqrtf(r0 * r0 + r1 * r1 + r2 * r2 + 1e-8f);
        {
            float c1 = (20.f / 35.f) * lane;
            float u = (r - c1) * 1.8f;
            s[OFF_INVT + (64 + lane) * 65 + p] = __expf(-u * u);   // rbf 0..31
            if (lane < 4) {
                float c2 = (20.f / 35.f) * (lane + 32);
                float u2 = (r - c2) * 1.8f;
                s[OFF_INVT + (96 + lane) * 65 + p] = __expf(-u2 * u2);  // rbf 32..35
            }
        }
        if (lane < 3) {
            float rel = (lane == 0) ? r0 : ((lane == 1) ? r1 : r2);
            s[OFF_RELHAT + p * 3 + lane] = rel / r;
            float a0 = xyz[j * 9 + lane * 3 + 0] - cj0;
            float a1 = xyz[j * 9 + lane * 3 + 1] - cj1;
            float a2 = xyz[j * 9 + lane * 3 + 2] - cj2;
            s[OFF_INVT + (100 + lane) * 65 + p] = sqrtf(a0 * a0 + a1 * a1 + a2 * a2 + 1e-8f);
        }
    }
    __syncthreads();

    int row = ((w & 1) << 5) | lane;  // pair index handled by this lane in GEMMs

    // ---- GEMM1: E_pre[64x32] = PN[64x128] @ W_e1 + b_e1 -> raw into invT rows 32..63 ----
    {
        int col0 = (w >> 1) * 8;
        float acc[8];
#pragma unroll
        for (int jj = 0; jj < 8; jj++) acc[jj] = s[OFF_BE1 + col0 + jj];
        for (int c = 0; c < 128; c++) {
            float a = s[OFF_BUF + c * 65 + row];
            const float4* wp = (const float4*)&s[OFF_WE1 + c * 32 + col0];
            float4 w0 = wp[0], w1 = wp[1];
            acc[0] = fmaf(a, w0.x, acc[0]); acc[1] = fmaf(a, w0.y, acc[1]);
            acc[2] = fmaf(a, w0.z, acc[2]); acc[3] = fmaf(a, w0.w, acc[3]);
            acc[4] = fmaf(a, w1.x, acc[4]); acc[5] = fmaf(a, w1.y, acc[5]);
            acc[6] = fmaf(a, w1.z, acc[6]); acc[7] = fmaf(a, w1.w, acc[7]);
        }
#pragma unroll
        for (int jj = 0; jj < 8; jj++)
            s[OFF_INVT + (32 + col0 + jj) * 65 + row] = acc[jj];
    }
    __syncthreads();

    // ---- LN over e_pre (32) per pair -> efeat in place ----
    for (int t = 0; t < 8; t++) {
        int p = t * 8 + w;
        float x = s[OFF_INVT + (32 + lane) * 65 + p];
        float mu = wsum(x) * (1.f / 32.f);
        float d = x - mu;
        float rs = rsqrtf(wsum(d * d) * (1.f / 32.f) + 1e-5f);
        s[OFF_INVT + (32 + lane) * 65 + p] = d * rs * s[OFF_GNE1 + lane] + s[OFF_BNE1 + lane];
    }
    __syncthreads();

    // ---- GEMM2: H[64x64] = relu(hbase + INV[64x103] @ W1[32:,:]) -> hT in BUF ----
    {
        int col0 = (w >> 1) * 16;
        float acc[16];
#pragma unroll
        for (int jj = 0; jj < 16; jj++) acc[jj] = s[OFF_HBASE + col0 + jj];
        for (int cc = 0; cc < 103; cc++) {
            float a = s[OFF_INVT + cc * 65 + row];
            const float4* wp = (const float4*)&s[OFF_W1 + (32 + cc) * 64 + col0];
            float4 w0 = wp[0], w1 = wp[1], w2v = wp[2], w3 = wp[3];
            acc[0]  = fmaf(a, w0.x, acc[0]);  acc[1]  = fmaf(a, w0.y, acc[1]);
            acc[2]  = fmaf(a, w0.z, acc[2]);  acc[3]  = fmaf(a, w0.w, acc[3]);
            acc[4]  = fmaf(a, w1.x, acc[4]);  acc[5]  = fmaf(a, w1.y, acc[5]);
            acc[6]  = fmaf(a, w1.z, acc[6]);  acc[7]  = fmaf(a, w1.w, acc[7]);
            acc[8]  = fmaf(a, w2v.x, acc[8]); acc[9]  = fmaf(a, w2v.y, acc[9]);
            acc[10] = fmaf(a, w2v.z, acc[10]); acc[11] = fmaf(a, w2v.w, acc[11]);
            acc[12] = fmaf(a, w3.x, acc[12]); acc[13] = fmaf(a, w3.y, acc[13]);
            acc[14] = fmaf(a, w3.z, acc[14]); acc[15] = fmaf(a, w3.w, acc[15]);
        }
#pragma unroll
        for (int jj = 0; jj < 16; jj++)
            s[OFF_BUF + (col0 + jj) * 65 + row] = fmaxf(acc[jj], 0.f);
    }
    __syncthreads();

    // ---- GEMM3: M[64x38] = H @ W2 + b2 ; reduce m0, stash gv/gd ----
    {
        int col0 = (w >> 1) * 12;
        float acc[12];
#pragma unroll
        for (int jj = 0; jj < 12; jj++) acc[jj] = s[OFF_B2P + col0 + jj];
        for (int h = 0; h < 64; h++) {
            float a = s[OFF_BUF + h * 65 + row];
            const float4* wp = (const float4*)&s[OFF_W2P + h * 48 + col0];
            float4 w0 = wp[0], w1 = wp[1], w2v = wp[2];
            acc[0]  = fmaf(a, w0.x, acc[0]);  acc[1]  = fmaf(a, w0.y, acc[1]);
            acc[2]  = fmaf(a, w0.z, acc[2]);  acc[3]  = fmaf(a, w0.w, acc[3]);
            acc[4]  = fmaf(a, w1.x, acc[4]);  acc[5]  = fmaf(a, w1.y, acc[5]);
            acc[6]  = fmaf(a, w1.z, acc[6]);  acc[7]  = fmaf(a, w1.w, acc[7]);
            acc[8]  = fmaf(a, w2v.x, acc[8]); acc[9]  = fmaf(a, w2v.y, acc[9]);
            acc[10] = fmaf(a, w2v.z, acc[10]); acc[11] = fmaf(a, w2v.w, acc[11]);
        }
#pragma unroll
        for (int jj = 0; jj < 12; jj++) {
            int cg = col0 + jj;
            if (cg < 32) {
                float red = wsum(acc[jj]);          // sum over this warp's 32 pairs
                if (lane == 0) atomicAdd(&s[OFF_M0S + cg], red);
            } else if (cg < 38) {
                s[OFF_GVGD + row * 6 + (cg - 32)] = acc[jj];
            }
        }
    }
    __syncthreads();

    // ---- out1 accumulation over pairs ----
    if (tid < 64) {
        int p = tid;
        int j = ((const int*)(s + OFF_NBR))[p];
        float cj0 = xyz[j * 9 + 3], cj1 = xyz[j * 9 + 4], cj2 = xyz[j * 9 + 5];
        float v1[3][3];
#pragma unroll
        for (int c = 0; c < 3; c++) {
            v1[c][0] = xyz[j * 9 + c * 3 + 0] - cj0;
            v1[c][1] = xyz[j * 9 + c * 3 + 1] - cj1;
            v1[c][2] = xyz[j * 9 + c * 3 + 2] - cj2;
        }
        float rh[3] = { s[OFF_RELHAT + p * 3 + 0], s[OFF_RELHAT + p * 3 + 1], s[OFF_RELHAT + p * 3 + 2] };
#pragma unroll
        for (int o = 0; o < 3; o++) {
            float gvv = s[OFF_GVGD + p * 6 + o];
            float gdd = s[OFF_GVGD + p * 6 + 3 + o];
            float wv0 = s[OFF_WV + o * 3 + 0], wv1 = s[OFF_WV + o * 3 + 1], wv2 = s[OFF_WV + o * 3 + 2];
#pragma unroll
            for (int d = 0; d < 3; d++) {
                float vm = wv0 * v1[0][d] + wv1 * v1[1][d] + wv2 * v1[2][d];
                atomicAdd(&s[OFF_O1S + o * 3 + d], gvv * vm + gdd * rh[d]);
            }
        }
    }
    __syncthreads();

    // ---- epilogue: out0/lddt + xyz_new ----
    if (tid < 32) {
        float acc = s[OFF_M0S + lane] * (1.f / KNN);
        for (int c = 0; c < 32; c++)
            acc = fmaf(s[OFF_NODEI + c], Wself[c * 32 + lane], acc);
        float mu = wsum(acc) * (1.f / 32.f);
        float d = acc - mu;
        float rs = rsqrtf(wsum(d * d) * (1.f / 32.f) + 1e-5f);
        float y = d * rs * g_state[lane] + b_state[lane];
        float tot = wsum(y * W_lddt[lane]);
        if (lane == 0)
            out[LQ * 9 + l] = 1.f / (1.f + expf(-(tot + b_lddt[0])));
        if (lane < 9) {
            int o = lane / 3, dd = lane % 3;
            float o1 = s[OFF_O1S + lane] * (1.f / KNN);
            float can = s[OFF_CA + dd] + s[OFF_O1S + 3 + dd] * (1.f / KNN);
            float val = o1 + ((l == 0) ? 0.f : can);
            out[(l * 3 + o) * 3 + dd] = val;
        }
    }
}

// ---------------- launch ----------------
extern "C" void kernel_launch(void* const* d_in, const int* in_sizes, int n_in,
                              void* d_out, int out_size)
{
    const float* xyz     = (const float*)d_in[0];
    const float* state   = (const float*)d_in[1];
    const float* msa     = (const float*)d_in[2];
    const float* pair    = (const float*)d_in[3];
    const float* seq1hot = (const float*)d_in[4];
    const float* g_msa   = (const float*)d_in[8];
    const float* b_msa   = (const float*)d_in[9];
    const float* g_pair  = (const float*)d_in[10];
    const float* b_pair  = (const float*)d_in[11];
    const float* g_state = (const float*)d_in[12];
    const float* b_state = (const float*)d_in[13];
    const float* W_x     = (const float*)d_in[14];
    const float* b_x     = (const float*)d_in[15];
    const float* g_node  = (const float*)d_in[16];
    const float* b_node  = (const float*)d_in[17];
    const float* W_e1    = (const float*)d_in[18];
    const float* b_e1    = (const float*)d_in[19];
    const float* g_ne1   = (const float*)d_in[20];
    const float* b_ne1   = (const float*)d_in[21];
    const float* W1      = (const float*)d_in[22];
    const float* b1      = (const float*)d_in[23];
    const float* W2      = (const float*)d_in[24];
    const float* b2      = (const float*)d_in[25];
    const float* Wv      = (const float*)d_in[26];
    const float* Wself   = (const float*)d_in[27];
    const float* W_lddt  = (const float*)d_in[28];
    const float* b_lddt  = (const float*)d_in[29];
    float* out = (float*)d_out;

    cudaFuncSetAttribute(pair_kernel, cudaFuncAttributeMaxDynamicSharedMemorySize,
                         SMEMF * (int)sizeof(float));

    node_kernel<<<LQ, 32>>>(msa, seq1hot, state, g_msa, b_msa, g_state, b_state,
                            W_x, b_x, g_node, b_node);
    topk_kernel<<<LQ, 256>>>(xyz);
    pair_kernel<<<LQ, 256, SMEMF * sizeof(float)>>>(
        xyz, pair, g_pair, b_pair, W_e1, b_e1, g_ne1, b_ne1,
        W1, b1, W2, b2, Wv, Wself, W_lddt, b_lddt, g_state, b_state, out);
}

// round 3
// speedup vs baseline: 1.2283x; 1.2283x over previous
#include <cuda_runtime.h>
#include <math.h>

#define LQ    512
#define KNN   64
#define DM    256
#define DP    128
#define DS    32
#define NL0   32
#define NRBF  36
#define MH    64
#define MOUT  38

// ---------------- scratch (static device arrays; no allocation) ----------------
__device__ float g_node_feat[LQ * NL0];
__device__ int   g_nbr[LQ * KNN];
__device__ float g_W2pad[MH * 48];
__device__ float g_b2pad[48];

__device__ __forceinline__ float wsum(float v) {
#pragma unroll
    for (int o = 16; o; o >>= 1) v += __shfl_xor_sync(0xffffffffu, v, o);
    return v;
}

// ---------------- Kernel A: fused topk (blocks 0..511) + node features (512..575) + W2 pad (576) ----------------
__global__ void __launch_bounds__(256) prep_kernel(
    const float* __restrict__ xyz,
    const float* __restrict__ msa, const float* __restrict__ seq1hot,
    const float* __restrict__ state,
    const float* __restrict__ g_msa, const float* __restrict__ b_msa,
    const float* __restrict__ g_state, const float* __restrict__ b_state,
    const float* __restrict__ W_x, const float* __restrict__ b_x,
    const float* __restrict__ g_node, const float* __restrict__ b_node,
    const float* __restrict__ W2, const float* __restrict__ b2)
{
    __shared__ __align__(16) float smem_f[2560];
    int tid = threadIdx.x;
    int w = tid >> 5, lane = tid & 31;

    if (blockIdx.x < LQ) {
        // ---- topk: bitonic sort of 512 (d2,idx) keys ----
        int i = blockIdx.x;
        float* sca = smem_f;                                      // 1536 floats
        unsigned long long* keys = (unsigned long long*)(smem_f + 1536);  // 512 u64

        for (int j = tid; j < LQ; j += 256) {
            sca[j * 3 + 0] = xyz[j * 9 + 3];
            sca[j * 3 + 1] = xyz[j * 9 + 4];
            sca[j * 3 + 2] = xyz[j * 9 + 5];
        }
        __syncthreads();
        float cx = sca[i * 3 + 0], cy = sca[i * 3 + 1], cz = sca[i * 3 + 2];
        for (int j = tid; j < LQ; j += 256) {
            float dx = sca[j * 3 + 0] - cx, dy = sca[j * 3 + 1] - cy, dz = sca[j * 3 + 2] - cz;
            float d2 = dx * dx + dy * dy + dz * dz;
            if (j == i) d2 += 1e9f;
            keys[j] = (((unsigned long long)__float_as_uint(d2)) << 32) | (unsigned)j;
        }
        for (int k = 2; k <= LQ; k <<= 1) {
            for (int j = k >> 1; j > 0; j >>= 1) {
                __syncthreads();
                for (int t = tid; t < LQ; t += 256) {
                    int ixj = t ^ j;
                    if (ixj > t) {
                        unsigned long long a = keys[t], b = keys[ixj];
                        bool up = ((t & k) == 0);
                        bool sw = up ? (a > b) : (a < b);
                        if (sw) { keys[t] = b; keys[ixj] = a; }
                    }
                }
            }
        }
        __syncthreads();
        if (tid < KNN) g_nbr[i * KNN + tid] = (int)(keys[tid] & 0xffffffffull);
    } else if (blockIdx.x < LQ + 64) {
        // ---- node features: 8 residues per block, one per warp ----
        int l = (blockIdx.x - LQ) * 8 + w;
        float* sx = smem_f + w * 312;   // 309 used

        float m[8]; float s0 = 0.f;
#pragma unroll
        for (int q = 0; q < 8; q++) { m[q] = msa[l * DM + lane + 32 * q]; s0 += m[q]; }
        float mu = wsum(s0) * (1.f / DM);
        float v0 = 0.f;
#pragma unroll
        for (int q = 0; q < 8; q++) { float d = m[q] - mu; v0 += d * d; }
        float rs = rsqrtf(wsum(v0) * (1.f / DM) + 1e-5f);
#pragma unroll
        for (int q = 0; q < 8; q++) {
            int c = lane + 32 * q;
            sx[c] = (m[q] - mu) * rs * g_msa[c] + b_msa[c];
        }
        if (lane < 21) sx[DM + lane] = seq1hot[l * 21 + lane];
        {
            float st = state[l * DS + lane];
            float mu2 = wsum(st) * (1.f / DS);
            float d = st - mu2;
            float rs2 = rsqrtf(wsum(d * d) * (1.f / DS) + 1e-5f);
            sx[DM + 21 + lane] = d * rs2 * g_state[lane] + b_state[lane];
        }
        __syncwarp();

        // 309 x 32 matvec, 4 accumulators to break the FMA chain
        float a0 = b_x[lane], a1 = 0.f, a2 = 0.f, a3 = 0.f;
        for (int c = 0; c < 308; c += 4) {
            a0 = fmaf(sx[c + 0], __ldg(W_x + (c + 0) * NL0 + lane), a0);
            a1 = fmaf(sx[c + 1], __ldg(W_x + (c + 1) * NL0 + lane), a1);
            a2 = fmaf(sx[c + 2], __ldg(W_x + (c + 2) * NL0 + lane), a2);
            a3 = fmaf(sx[c + 3], __ldg(W_x + (c + 3) * NL0 + lane), a3);
        }
        float acc = (a0 + a1) + (a2 + a3) + sx[308] * __ldg(W_x + 308 * NL0 + lane);

        float mu3 = wsum(acc) * (1.f / NL0);
        float d3 = acc - mu3;
        float rs3 = rsqrtf(wsum(d3 * d3) * (1.f / NL0) + 1e-5f);
        g_node_feat[l * NL0 + lane] = d3 * rs3 * g_node[lane] + b_node[lane];
    } else {
        // ---- pad W2 [64x38] -> [64x48], b2 -> [48] ----
        for (int i = tid; i < MH * 48; i += 256) {
            int h = i / 48, c = i - h * 48;
            g_W2pad[i] = (c < MOUT) ? W2[h * MOUT + c] : 0.f;
        }
        if (tid < 48) g_b2pad[tid] = (tid < MOUT) ? b2[tid] : 0.f;
    }
}

// ---------------- Kernel B: per-residue edge MLP + epilogue ----------------
// smem layout (floats) — weights now come from global, only activations in smem
#define OFF_INVT   0        // 103*65
#define OFF_BUF    6695     // max(pnT 128*65, hT 64*65) = 8320
#define OFF_HBASE  15015    // 64
#define OFF_GNE1   15079    // 32
#define OFF_BNE1   15111    // 32
#define OFF_GP     15143    // 128
#define OFF_BP     15271    // 128
#define OFF_NODEI  15399    // 32
#define OFF_CA     15431    // 4
#define OFF_WV     15435    // 12
#define OFF_NBR    15447    // 64 (ints)
#define OFF_RELHAT 15511    // 64*3
#define OFF_GVGD   15703    // 64*6
#define OFF_M0S    16087    // 32
#define OFF_O1S    16119    // 12
#define SMEMF      16131

__global__ void __launch_bounds__(256, 3) pair_kernel(
    const float* __restrict__ xyz, const float* __restrict__ pair,
    const float* __restrict__ g_pair, const float* __restrict__ b_pair,
    const float* __restrict__ W_e1, const float* __restrict__ b_e1,
    const float* __restrict__ g_ne1, const float* __restrict__ b_ne1,
    const float* __restrict__ W1, const float* __restrict__ b1,
    const float* __restrict__ Wv, const float* __restrict__ Wself,
    const float* __restrict__ W_lddt, const float* __restrict__ b_lddt,
    const float* __restrict__ g_state, const float* __restrict__ b_state,
    float* __restrict__ out)
{
    extern __shared__ float s[];
    int l = blockIdx.x;
    int tid = threadIdx.x;
    int w = tid >> 5, lane = tid & 31;

    // ---- stage small vectors ----
    if (tid < 32) {
        s[OFF_GNE1 + tid] = g_ne1[tid];
        s[OFF_BNE1 + tid] = b_ne1[tid];
        s[OFF_NODEI + tid] = g_node_feat[l * NL0 + tid];
        s[OFF_M0S + tid] = 0.f;
    }
    if (tid < 12) s[OFF_O1S + tid] = 0.f;
    if (tid < 128) { s[OFF_GP + tid] = g_pair[tid]; s[OFF_BP + tid] = b_pair[tid]; }
    if (tid < 64) ((int*)(s + OFF_NBR))[tid] = g_nbr[l * KNN + tid];
    if (tid < 3) s[OFF_CA + tid] = xyz[l * 9 + 3 + tid];
    if (tid < 9) s[OFF_WV + tid] = Wv[tid];
    __syncthreads();

    // ---- hbase: node_i part of MLP1 (same for all pairs) ----
    if (tid < 64) {
        float a = b1[tid];
#pragma unroll
        for (int c = 0; c < 32; c++)
            a = fmaf(s[OFF_NODEI + c], __ldg(W1 + c * 64 + tid), a);
        s[OFF_HBASE + tid] = a;
    }

    // ---- per-pair prep: pair-row LN -> pnT, node_j, rbf, vnorm, relhat ----
    float ca0 = s[OFF_CA + 0], ca1 = s[OFF_CA + 1], ca2 = s[OFF_CA + 2];
    for (int t = 0; t < 8; t++) {
        int p = t * 8 + w;
        int j = ((const int*)(s + OFF_NBR))[p];
        const float* prow = pair + ((size_t)l * LQ + j) * DP;
        float pv[4]; float sm = 0.f;
#pragma unroll
        for (int q = 0; q < 4; q++) { pv[q] = prow[lane + 32 * q]; sm += pv[q]; }
        float mu = wsum(sm) * (1.f / DP);
        float vv = 0.f;
#pragma unroll
        for (int q = 0; q < 4; q++) { float d = pv[q] - mu; vv += d * d; }
        float rs = rsqrtf(wsum(vv) * (1.f / DP) + 1e-5f);
#pragma unroll
        for (int q = 0; q < 4; q++) {
            int c = lane + 32 * q;
            s[OFF_BUF + c * 65 + p] = (pv[q] - mu) * rs * s[OFF_GP + c] + s[OFF_BP + c];
        }
        s[OFF_INVT + lane * 65 + p] = g_node_feat[j * NL0 + lane];
        float cj0 = xyz[j * 9 + 3], cj1 = xyz[j * 9 + 4], cj2 = xyz[j * 9 + 5];
        float r0 = cj0 - ca0, r1 = cj1 - ca1, r2 = cj2 - ca2;
        float r = sqrtf(r0 * r0 + r1 * r1 + r2 * r2 + 1e-8f);
        {
            float c1 = (20.f / 35.f) * lane;
            float u = (r - c1) * 1.8f;
            s[OFF_INVT + (64 + lane) * 65 + p] = __expf(-u * u);
            if (lane < 4) {
                float c2 = (20.f / 35.f) * (lane + 32);
                float u2 = (r - c2) * 1.8f;
                s[OFF_INVT + (96 + lane) * 65 + p] = __expf(-u2 * u2);
            }
        }
        if (lane < 3) {
            float rel = (lane == 0) ? r0 : ((lane == 1) ? r1 : r2);
            s[OFF_RELHAT + p * 3 + lane] = rel / r;
            float a0 = xyz[j * 9 + lane * 3 + 0] - cj0;
            float a1 = xyz[j * 9 + lane * 3 + 1] - cj1;
            float a2 = xyz[j * 9 + lane * 3 + 2] - cj2;
            s[OFF_INVT + (100 + lane) * 65 + p] = sqrtf(a0 * a0 + a1 * a1 + a2 * a2 + 1e-8f);
        }
    }
    __syncthreads();

    int row = ((w & 1) << 5) | lane;

    // ---- GEMM1: E_pre[64x32] = PN[64x128] @ W_e1 + b_e1 -> invT rows 32..63 ----
    {
        int col0 = (w >> 1) * 8;
        float acc[8];
#pragma unroll
        for (int jj = 0; jj < 8; jj++) acc[jj] = __ldg(b_e1 + col0 + jj);
#pragma unroll 2
        for (int c = 0; c < 128; c++) {
            float a = s[OFF_BUF + c * 65 + row];
            const float4* wp = (const float4*)(W_e1 + c * 32 + col0);
            float4 w0 = __ldg(wp), w1 = __ldg(wp + 1);
            acc[0] = fmaf(a, w0.x, acc[0]); acc[1] = fmaf(a, w0.y, acc[1]);
            acc[2] = fmaf(a, w0.z, acc[2]); acc[3] = fmaf(a, w0.w, acc[3]);
            acc[4] = fmaf(a, w1.x, acc[4]); acc[5] = fmaf(a, w1.y, acc[5]);
            acc[6] = fmaf(a, w1.z, acc[6]); acc[7] = fmaf(a, w1.w, acc[7]);
        }
#pragma unroll
        for (int jj = 0; jj < 8; jj++)
            s[OFF_INVT + (32 + col0 + jj) * 65 + row] = acc[jj];
    }
    __syncthreads();

    // ---- LN over e_pre (32) per pair ----
    for (int t = 0; t < 8; t++) {
        int p = t * 8 + w;
        float x = s[OFF_INVT + (32 + lane) * 65 + p];
        float mu = wsum(x) * (1.f / 32.f);
        float d = x - mu;
        float rs = rsqrtf(wsum(d * d) * (1.f / 32.f) + 1e-5f);
        s[OFF_INVT + (32 + lane) * 65 + p] = d * rs * s[OFF_GNE1 + lane] + s[OFF_BNE1 + lane];
    }
    __syncthreads();

    // ---- GEMM2: H[64x64] = relu(hbase + INV[64x103] @ W1[32:,:]) ----
    {
        int col0 = (w >> 1) * 16;
        const float* w1base = W1 + 32 * 64 + col0;
        float acc[16];
#pragma unroll
        for (int jj = 0; jj < 16; jj++) acc[jj] = s[OFF_HBASE + col0 + jj];
#pragma unroll 2
        for (int cc = 0; cc < 103; cc++) {
            float a = s[OFF_INVT + cc * 65 + row];
            const float4* wp = (const float4*)(w1base + cc * 64);
            float4 w0 = __ldg(wp), w1v = __ldg(wp + 1), w2v = __ldg(wp + 2), w3 = __ldg(wp + 3);
            acc[0]  = fmaf(a, w0.x, acc[0]);  acc[1]  = fmaf(a, w0.y, acc[1]);
            acc[2]  = fmaf(a, w0.z, acc[2]);  acc[3]  = fmaf(a, w0.w, acc[3]);
            acc[4]  = fmaf(a, w1v.x, acc[4]); acc[5]  = fmaf(a, w1v.y, acc[5]);
            acc[6]  = fmaf(a, w1v.z, acc[6]); acc[7]  = fmaf(a, w1v.w, acc[7]);
            acc[8]  = fmaf(a, w2v.x, acc[8]); acc[9]  = fmaf(a, w2v.y, acc[9]);
            acc[10] = fmaf(a, w2v.z, acc[10]); acc[11] = fmaf(a, w2v.w, acc[11]);
            acc[12] = fmaf(a, w3.x, acc[12]); acc[13] = fmaf(a, w3.y, acc[13]);
            acc[14] = fmaf(a, w3.z, acc[14]); acc[15] = fmaf(a, w3.w, acc[15]);
        }
#pragma unroll
        for (int jj = 0; jj < 16; jj++)
            s[OFF_BUF + (col0 + jj) * 65 + row] = fmaxf(acc[jj], 0.f);
    }
    __syncthreads();

    // ---- GEMM3: M[64x38] = H @ W2 + b2 (padded to 48) ----
    {
        int col0 = (w >> 1) * 12;
        float acc[12];
#pragma unroll
        for (int jj = 0; jj < 12; jj++) acc[jj] = g_b2pad[col0 + jj];
#pragma unroll 2
        for (int h = 0; h < 64; h++) {
            float a = s[OFF_BUF + h * 65 + row];
            const float4* wp = (const float4*)(g_W2pad + h * 48 + col0);
            float4 w0 = __ldg(wp), w1v = __ldg(wp + 1), w2v = __ldg(wp + 2);
            acc[0]  = fmaf(a, w0.x, acc[0]);  acc[1]  = fmaf(a, w0.y, acc[1]);
            acc[2]  = fmaf(a, w0.z, acc[2]);  acc[3]  = fmaf(a, w0.w, acc[3]);
            acc[4]  = fmaf(a, w1v.x, acc[4]); acc[5]  = fmaf(a, w1v.y, acc[5]);
            acc[6]  = fmaf(a, w1v.z, acc[6]); acc[7]  = fmaf(a, w1v.w, acc[7]);
            acc[8]  = fmaf(a, w2v.x, acc[8]); acc[9]  = fmaf(a, w2v.y, acc[9]);
            acc[10] = fmaf(a, w2v.z, acc[10]); acc[11] = fmaf(a, w2v.w, acc[11]);
        }
#pragma unroll
        for (int jj = 0; jj < 12; jj++) {
            int cg = col0 + jj;
            if (cg < 32) {
                float red = wsum(acc[jj]);
                if (lane == 0) atomicAdd(&s[OFF_M0S + cg], red);
            } else if (cg < 38) {
                s[OFF_GVGD + row * 6 + (cg - 32)] = acc[jj];
            }
        }
    }
    __syncthreads();

    // ---- out1 accumulation over pairs ----
    if (tid < 64) {
        int p = tid;
        int j = ((const int*)(s + OFF_NBR))[p];
        float cj0 = xyz[j * 9 + 3], cj1 = xyz[j * 9 + 4], cj2 = xyz[j * 9 + 5];
        float v1[3][3];
#pragma unroll
        for (int c = 0; c < 3; c++) {
            v1[c][0] = xyz[j * 9 + c * 3 + 0] - cj0;
            v1[c][1] = xyz[j * 9 + c * 3 + 1] - cj1;
            v1[c][2] = xyz[j * 9 + c * 3 + 2] - cj2;
        }
        float rh[3] = { s[OFF_RELHAT + p * 3 + 0], s[OFF_RELHAT + p * 3 + 1], s[OFF_RELHAT + p * 3 + 2] };
#pragma unroll
        for (int o = 0; o < 3; o++) {
            float gvv = s[OFF_GVGD + p * 6 + o];
            float gdd = s[OFF_GVGD + p * 6 + 3 + o];
            float wv0 = s[OFF_WV + o * 3 + 0], wv1 = s[OFF_WV + o * 3 + 1], wv2 = s[OFF_WV + o * 3 + 2];
#pragma unroll
            for (int d = 0; d < 3; d++) {
                float vm = wv0 * v1[0][d] + wv1 * v1[1][d] + wv2 * v1[2][d];
                atomicAdd(&s[OFF_O1S + o * 3 + d], gvv * vm + gdd * rh[d]);
            }
        }
    }
    __syncthreads();

    // ---- epilogue: out0/lddt + xyz_new ----
    if (tid < 32) {
        float acc = s[OFF_M0S + lane] * (1.f / KNN);
        for (int c = 0; c < 32; c++)
            acc = fmaf(s[OFF_NODEI + c], __ldg(Wself + c * 32 + lane), acc);
        float mu = wsum(acc) * (1.f / 32.f);
        float d = acc - mu;
        float rs = rsqrtf(wsum(d * d) * (1.f / 32.f) + 1e-5f);
        float y = d * rs * g_state[lane] + b_state[lane];
        float tot = wsum(y * W_lddt[lane]);
        if (lane == 0)
            out[LQ * 9 + l] = 1.f / (1.f + expf(-(tot + b_lddt[0])));
        if (lane < 9) {
            int o = lane / 3, dd = lane % 3;
            float o1 = s[OFF_O1S + lane] * (1.f / KNN);
            float can = s[OFF_CA + dd] + s[OFF_O1S + 3 + dd] * (1.f / KNN);
            float val = o1 + ((l == 0) ? 0.f : can);
            out[(l * 3 + o) * 3 + dd] = val;
        }
    }
}

// ---------------- launch ----------------
extern "C" void kernel_launch(void* const* d_in, const int* in_sizes, int n_in,
                              void* d_out, int out_size)
{
    const float* xyz     = (const float*)d_in[0];
    const float* state   = (const float*)d_in[1];
    const float* msa     = (const float*)d_in[2];
    const float* pair    = (const float*)d_in[3];
    const float* seq1hot = (const float*)d_in[4];
    const float* g_msa   = (const float*)d_in[8];
    const float* b_msa   = (const float*)d_in[9];
    const float* g_pair  = (const float*)d_in[10];
    const float* b_pair  = (const float*)d_in[11];
    const float* g_state = (const float*)d_in[12];
    const float* b_state = (const float*)d_in[13];
    const float* W_x     = (const float*)d_in[14];
    const float* b_x     = (const float*)d_in[15];
    const float* g_node  = (const float*)d_in[16];
    const float* b_node  = (const float*)d_in[17];
    const float* W_e1    = (const float*)d_in[18];
    const float* b_e1    = (const float*)d_in[19];
    const float* g_ne1   = (const float*)d_in[20];
    const float* b_ne1   = (const float*)d_in[21];
    const float* W1      = (const float*)d_in[22];
    const float* b1      = (const float*)d_in[23];
    const float* W2      = (const float*)d_in[24];
    const float* b2      = (const float*)d_in[25];
    const float* Wv      = (const float*)d_in[26];
    const float* Wself   = (const float*)d_in[27];
    const float* W_lddt  = (const float*)d_in[28];
    const float* b_lddt  = (const float*)d_in[29];
    float* out = (float*)d_out;

    cudaFuncSetAttribute(pair_kernel, cudaFuncAttributeMaxDynamicSharedMemorySize,
                         SMEMF * (int)sizeof(float));

    prep_kernel<<<LQ + 64 + 1, 256>>>(xyz, msa, seq1hot, state,
                                      g_msa, b_msa, g_state, b_state,
                                      W_x, b_x, g_node, b_node, W2, b2);
    pair_kernel<<<LQ, 256, SMEMF * sizeof(float)>>>(
        xyz, pair, g_pair, b_pair, W_e1, b_e1, g_ne1, b_ne1,
        W1, b1, Wv, Wself, W_lddt, b_lddt, g_state, b_state, out);
}